// round 17
// baseline (speedup 1.0000x reference)
#include <cuda_runtime.h>
#include <cuda_fp16.h>
#include <math.h>
#include <stdint.h>

// ---------------------------------------------------------------------------
// ResidualDenoiser via HMMA (mma.sync fp16, fp32 acc), pure fp16 inference.
// Mainloop loads via cp.async.bulk (1D bulk copy, mbarrier complete_tx):
// one 128B row per thread per stage instead of 8x cp.async 16B.
// Layers 0-2: CTA 128x128, 256 thr, KC=64, 3 stages, 2 CTAs/SM.
// Layer 3:    CTA 128x64.
//
// Activation buffer (width 3328, fp16): [ h2 (1024) | h1 (1024) | h0 (1024) | x (256) ]
// ---------------------------------------------------------------------------

#define B_ROWS 8192
#define ACT_W  3328
#define NSEG   10
#define EPS    1e-5f

#define TBM 128
#define TBN 128
#define KC  64
#define ROWB 144                 // padded row stride (bytes) for 128B of k data
#define TILEB (128 * ROWB)       // 18432 bytes per 128-row tile
#define STAGEB (2 * TILEB)       // A, W : 36864
#define SMEM_MAIN (3 * STAGEB + 64)    // 110656 (3 stages + mbarriers)

#define L3_TBN 64
#define L3_STAGEB (TILEB + L3_TBN * ROWB)    // 27648
#define SMEM_L3 (3 * L3_STAGEB + 64)         // 83008

// weight concat offsets (elements)
#define WOFF0 0
#define WOFF1 262144
#define WOFF2 1572864
#define WOFF3 3932160
#define WTOT  4784128

__device__ __half g_act[(size_t)B_ROWS * ACT_W];
__device__ __half g_w[WTOT];
__device__ float  g_logits[(size_t)B_ROWS * 256];

__device__ __forceinline__ uint32_t smem_u32(const void* p) {
    uint32_t a;
    asm("{ .reg .u64 t; cvta.to.shared.u64 t, %1; cvt.u32.u64 %0, t; }" : "=r"(a) : "l"(p));
    return a;
}

#define MBAR_INIT(mb, c) \
    asm volatile("mbarrier.init.shared.b64 [%0], %1;" :: "r"(mb), "r"(c) : "memory")
#define MBAR_EXPECT(mb, bytes) \
    asm volatile("mbarrier.arrive.expect_tx.shared.b64 _, [%0], %1;" :: "r"(mb), "r"(bytes) : "memory")
#define MBAR_WAIT(mb, ph) do {                                                  \
    uint32_t _done = 0;                                                         \
    while (!_done) {                                                            \
        asm volatile("{\n\t.reg .pred p;\n\t"                                   \
            "mbarrier.try_wait.parity.acquire.cta.shared::cta.b64 p, [%1], %2, 0x989680;\n\t" \
            "selp.b32 %0,1,0,p;\n\t}"                                           \
            : "=r"(_done) : "r"(mb), "r"(ph) : "memory");                       \
    }                                                                           \
} while (0)

#define BULK_G2S(dst, src, nbytes, mb) \
    asm volatile("cp.async.bulk.shared::cluster.global.mbarrier::complete_tx::bytes " \
        "[%0], [%1], %2, [%3];" \
        :: "r"(dst), "l"(src), "r"(nbytes), "r"(mb) : "memory")

#define LDSM_X4(r0, r1, r2, r3, a) \
    asm volatile("ldmatrix.sync.aligned.m8n8.x4.shared.b16 {%0,%1,%2,%3}, [%4];" \
        : "=r"(r0), "=r"(r1), "=r"(r2), "=r"(r3) : "r"(a))

#define MMA_F16(d, a, b) \
    asm volatile("mma.sync.aligned.m16n8k16.row.col.f32.f16.f16.f32 " \
        "{%0,%1,%2,%3}, {%4,%5,%6,%7}, {%8,%9}, {%0,%1,%2,%3};" \
        : "+f"((d)[0]), "+f"((d)[1]), "+f"((d)[2]), "+f"((d)[3]) \
        : "r"((a)[0]), "r"((a)[1]), "r"((a)[2]), "r"((a)[3]), \
          "r"((b)[0]), "r"((b)[1]))

// ---------------------------------------------------------------------------
// Layers 0-2 GEMM: CTA 128x128, warp tile 64x32, bulk-copy pipeline.
// bias + BN + ReLU -> fp16 out (row stride ACT_W).
// ---------------------------------------------------------------------------
__global__ __launch_bounds__(256, 2)
void mma_gemm_bn(const __half* __restrict__ A,
                 const __half* __restrict__ Wh,
                 const float* __restrict__ bias,
                 const float* __restrict__ gg, const float* __restrict__ be,
                 const float* __restrict__ rm, const float* __restrict__ rv,
                 __half* __restrict__ Ch, int K)
{
    extern __shared__ char smem[];
    const uint32_t sbuf = smem_u32(smem);
    const uint32_t mb   = sbuf + 3 * STAGEB;     // 3 mbarriers @ +0,+8,+16

    const int tid    = threadIdx.x;
    const int lane   = tid & 31;
    const int wid    = tid >> 5;
    const int warp_m = wid & 1;        // 2 warps over M (64 rows each)
    const int warp_n = wid >> 1;       // 4 warps over N (32 cols each)
    const int row0   = blockIdx.y * TBM;
    const int col0   = blockIdx.x * TBN;

    const int n_iter = K / KC;

    if (tid == 0) {
        MBAR_INIT(mb + 0, 1);
        MBAR_INIT(mb + 8, 1);
        MBAR_INIT(mb + 16, 1);
    }
    __syncthreads();

    float acc[4][4][4];
    #pragma unroll
    for (int i = 0; i < 4; i++)
        #pragma unroll
        for (int j = 0; j < 4; j++)
            #pragma unroll
            for (int l = 0; l < 4; l++)
                acc[i][j][l] = 0.f;

    // per-thread bulk-copy role: tid<128 -> A row tid; else W row tid-128
    const int  br  = tid & 127;
    const bool isA = tid < 128;
    const __half* srow = isA ? A  + (size_t)(row0 + br) * ACT_W
                             : Wh + (size_t)(col0 + br) * K;
    const uint32_t drow = (isA ? 0u : (uint32_t)TILEB) + (uint32_t)(br * ROWB);

    auto issue_stage = [&](int s) {
        const int slot = s - (s / 3) * 3;
        if (tid == 0) MBAR_EXPECT(mb + 8 * slot, 32768);
        BULK_G2S(sbuf + slot * STAGEB + drow, srow + s * KC, 128, mb + 8 * slot);
    };

    // ldmatrix per-lane base offsets
    const uint32_t a_off = (uint32_t)((warp_m * 64 + (lane & 15)) * ROWB + (lane >> 4) * 16);
    const uint32_t b_off = (uint32_t)((warp_n * 32 + (lane >> 4) * 8 + (lane & 7)) * ROWB
                                      + ((lane >> 3) & 1) * 16);

    issue_stage(0);
    issue_stage(1);

    for (int it = 0; it < n_iter; it++) {
        __syncthreads();                      // WAR: all reads of iter it-1 done
        if (it + 2 < n_iter) issue_stage(it + 2);
        const int q    = it / 3;
        const int slot = it - q * 3;
        MBAR_WAIT(mb + 8 * slot, q & 1);

        const uint32_t sb = sbuf + slot * STAGEB;
        #pragma unroll
        for (int kk = 0; kk < 4; kk++) {      // four k16 steps
            uint32_t ah[4][4], bh[4][2];
            #pragma unroll
            for (int mt = 0; mt < 4; mt++) {
                const uint32_t aa = sb + a_off + mt * (16 * ROWB) + kk * 32;
                LDSM_X4(ah[mt][0], ah[mt][1], ah[mt][2], ah[mt][3], aa);
            }
            #pragma unroll
            for (int bt = 0; bt < 2; bt++) {
                const uint32_t ba = sb + TILEB + b_off + bt * (16 * ROWB) + kk * 32;
                uint32_t r0, r1, r2, r3;
                LDSM_X4(r0, r1, r2, r3, ba);
                bh[bt * 2][0] = r0;     bh[bt * 2][1] = r1;
                bh[bt * 2 + 1][0] = r2; bh[bt * 2 + 1][1] = r3;
            }
            #pragma unroll
            for (int mt = 0; mt < 4; mt++)
                #pragma unroll
                for (int nt = 0; nt < 4; nt++)
                    MMA_F16(acc[mt][nt], ah[mt], bh[nt]);
        }
    }

    // ------------------------------ epilogue ------------------------------
    #pragma unroll
    for (int nt = 0; nt < 4; nt++) {
        const int f = col0 + warp_n * 32 + nt * 8 + (lane & 3) * 2;
        const float bs0 = bias[f], bs1 = bias[f + 1];
        const float sc0 = gg[f]     * rsqrtf(rv[f]     + EPS);
        const float sc1 = gg[f + 1] * rsqrtf(rv[f + 1] + EPS);
        const float sh0 = be[f]     - rm[f]     * sc0;
        const float sh1 = be[f + 1] - rm[f + 1] * sc1;
        #pragma unroll
        for (int mt = 0; mt < 4; mt++) {
            const int r = row0 + warp_m * 64 + mt * 16 + (lane >> 2);
            #pragma unroll
            for (int half = 0; half < 2; half++) {
                const int rr = r + half * 8;
                float v0 = acc[mt][nt][half * 2]     + bs0;
                float v1 = acc[mt][nt][half * 2 + 1] + bs1;
                v0 = fmaxf(fmaf(v0, sc0, sh0), 0.f);
                v1 = fmaxf(fmaf(v1, sc1, sh1), 0.f);
                __half2 hp; hp.x = __float2half(v0); hp.y = __float2half(v1);
                *reinterpret_cast<__half2*>(Ch + (size_t)rr * ACT_W + f) = hp;
            }
        }
    }
}

// ---------------------------------------------------------------------------
// Layer 3 GEMM: CTA 128x64, 256 threads, warp grid 4(M)x2(N), warp tile 32x32.
// bias only -> fp32 logits (row stride 256). Bulk-copy pipeline (192 rows).
// ---------------------------------------------------------------------------
__global__ __launch_bounds__(256, 2)
void mma_gemm_l3(const __half* __restrict__ A,
                 const __half* __restrict__ Wh,
                 const float* __restrict__ bias,
                 float* __restrict__ Cf, int K)
{
    extern __shared__ char smem[];
    const uint32_t sbuf = smem_u32(smem);
    const uint32_t mb   = sbuf + 3 * L3_STAGEB;

    const int tid    = threadIdx.x;
    const int lane   = tid & 31;
    const int wid    = tid >> 5;
    const int warp_m = wid & 3;        // 4 warps over M (32 rows each)
    const int warp_n = wid >> 2;       // 2 warps over N (32 cols each)
    const int row0   = blockIdx.y * TBM;
    const int col0   = blockIdx.x * L3_TBN;

    const int n_iter = K / KC;

    if (tid == 0) {
        MBAR_INIT(mb + 0, 1);
        MBAR_INIT(mb + 8, 1);
        MBAR_INIT(mb + 16, 1);
    }
    __syncthreads();

    float acc[2][4][4];
    #pragma unroll
    for (int i = 0; i < 2; i++)
        #pragma unroll
        for (int j = 0; j < 4; j++)
            #pragma unroll
            for (int l = 0; l < 4; l++)
                acc[i][j][l] = 0.f;

    // bulk roles: tid<128 -> A row tid; 128<=tid<192 -> W row tid-128
    const int  br  = tid & 127;
    const bool isA = tid < 128;
    const bool act = tid < 192;
    const __half* srow = isA ? A  + (size_t)(row0 + br) * ACT_W
                             : Wh + (size_t)(col0 + (br & 63)) * K;
    const uint32_t drow = (isA ? 0u : (uint32_t)TILEB) + (uint32_t)((isA ? br : (br & 63)) * ROWB);

    auto issue_stage = [&](int s) {
        const int slot = s - (s / 3) * 3;
        if (tid == 0) MBAR_EXPECT(mb + 8 * slot, 24576);
        if (act) BULK_G2S(sbuf + slot * L3_STAGEB + drow, srow + s * KC, 128, mb + 8 * slot);
    };

    const uint32_t a_off = (uint32_t)((warp_m * 32 + (lane & 15)) * ROWB + (lane >> 4) * 16);
    const uint32_t b_off = (uint32_t)((warp_n * 32 + (lane >> 4) * 8 + (lane & 7)) * ROWB
                                      + ((lane >> 3) & 1) * 16);

    issue_stage(0);
    issue_stage(1);

    for (int it = 0; it < n_iter; it++) {
        __syncthreads();
        if (it + 2 < n_iter) issue_stage(it + 2);
        const int q    = it / 3;
        const int slot = it - q * 3;
        MBAR_WAIT(mb + 8 * slot, q & 1);

        const uint32_t sb = sbuf + slot * L3_STAGEB;
        #pragma unroll
        for (int kk = 0; kk < 4; kk++) {
            uint32_t ah[2][4], bh[4][2];
            #pragma unroll
            for (int mt = 0; mt < 2; mt++) {
                const uint32_t aa = sb + a_off + mt * (16 * ROWB) + kk * 32;
                LDSM_X4(ah[mt][0], ah[mt][1], ah[mt][2], ah[mt][3], aa);
            }
            #pragma unroll
            for (int bt = 0; bt < 2; bt++) {
                const uint32_t ba = sb + TILEB + b_off + bt * (16 * ROWB) + kk * 32;
                uint32_t r0, r1, r2, r3;
                LDSM_X4(r0, r1, r2, r3, ba);
                bh[bt * 2][0] = r0;     bh[bt * 2][1] = r1;
                bh[bt * 2 + 1][0] = r2; bh[bt * 2 + 1][1] = r3;
            }
            #pragma unroll
            for (int mt = 0; mt < 2; mt++)
                #pragma unroll
                for (int nt = 0; nt < 4; nt++)
                    MMA_F16(acc[mt][nt], ah[mt], bh[nt]);
        }
    }

    #pragma unroll
    for (int nt = 0; nt < 4; nt++) {
        const int f = col0 + warp_n * 32 + nt * 8 + (lane & 3) * 2;
        const float bs0 = bias[f], bs1 = bias[f + 1];
        #pragma unroll
        for (int mt = 0; mt < 2; mt++) {
            const int r = row0 + warp_m * 32 + mt * 16 + (lane >> 2);
            #pragma unroll
            for (int half = 0; half < 2; half++) {
                const int rr = r + half * 8;
                float2 o;
                o.x = acc[mt][nt][half * 2]     + bs0;
                o.y = acc[mt][nt][half * 2 + 1] + bs1;
                *reinterpret_cast<float2*>(Cf + (size_t)rr * 256 + f) = o;
            }
        }
    }
}

// ---------------------------------------------------------------------------
// merged conversion: blocks [0,1024) convert x, blocks [1024,3360) weights
// ---------------------------------------------------------------------------
__global__ void cvt_all(const float* __restrict__ x,
                        const float* __restrict__ W0, const float* __restrict__ W1,
                        const float* __restrict__ W2, const float* __restrict__ W3)
{
    const int b = blockIdx.x;
    if (b < 1024) {
        const int i = (b * 256 + threadIdx.x) * 8;    // over 8192*256
        const int r = i >> 8;
        const int c = i & 255;
        float4 a = *reinterpret_cast<const float4*>(x + i);
        float4 d = *reinterpret_cast<const float4*>(x + i + 4);
        __half2 h[4];
        h[0] = __floats2half2_rn(a.x, a.y);
        h[1] = __floats2half2_rn(a.z, a.w);
        h[2] = __floats2half2_rn(d.x, d.y);
        h[3] = __floats2half2_rn(d.z, d.w);
        *reinterpret_cast<uint4*>(g_act + (size_t)r * ACT_W + 3072 + c) =
            *reinterpret_cast<uint4*>(h);
    } else {
        const int i = ((b - 1024) * 256 + threadIdx.x) * 8;   // over WTOT
        const float* src;
        int base;
        if (i < WOFF1)      { src = W0; base = WOFF0; }
        else if (i < WOFF2) { src = W1; base = WOFF1; }
        else if (i < WOFF3) { src = W2; base = WOFF2; }
        else                { src = W3; base = WOFF3; }
        const int j = i - base;
        float4 a = *reinterpret_cast<const float4*>(src + j);
        float4 d = *reinterpret_cast<const float4*>(src + j + 4);
        __half2 h[4];
        h[0] = __floats2half2_rn(a.x, a.y);
        h[1] = __floats2half2_rn(a.z, a.w);
        h[2] = __floats2half2_rn(d.x, d.y);
        h[3] = __floats2half2_rn(d.z, d.w);
        *reinterpret_cast<uint4*>(g_w + i) = *reinterpret_cast<uint4*>(h);
    }
}

// ---------------------------------------------------------------------------
// Segmented softmax: one block per row, 320 threads; warp s reduces segment s.
// ---------------------------------------------------------------------------
__global__ __launch_bounds__(320)
void seg_softmax_kernel(const int* __restrict__ seg_ids,
                        float* __restrict__ out)
{
    __shared__ float vals[256];
    __shared__ int   sseg[256];
    __shared__ int   segstart[NSEG];
    __shared__ int   segend[NSEG];
    __shared__ float smax[NSEG];
    __shared__ float ssum[NSEG];

    const int row  = blockIdx.x;
    const int t    = threadIdx.x;
    const int lane = t & 31;
    const int w    = t >> 5;           // 0..9

    float v = 0.f;
    int sg = 0;
    if (t < 256) {
        v  = g_logits[(size_t)row * 256 + t];
        sg = seg_ids[t];
        vals[t] = v;
        sseg[t] = sg;
    }
    __syncthreads();

    if (t < 256) {
        if (t == 0 || sseg[t - 1] != sg) segstart[sg] = t;
        if (t == 255 || sseg[t + 1] != sg) segend[sg] = t + 1;
    }
    __syncthreads();

    {
        const int s0 = segstart[w];
        const int s1 = segend[w];
        float m = -3.402823466e+38f;
        for (int i = s0 + lane; i < s1; i += 32) m = fmaxf(m, vals[i]);
        #pragma unroll
        for (int o = 16; o > 0; o >>= 1)
            m = fmaxf(m, __shfl_xor_sync(0xFFFFFFFFu, m, o));
        float sum = 0.f;
        for (int i = s0 + lane; i < s1; i += 32)
            sum += expf(vals[i] - m);
        #pragma unroll
        for (int o = 16; o > 0; o >>= 1)
            sum += __shfl_xor_sync(0xFFFFFFFFu, sum, o);
        if (lane == 0) { smax[w] = m; ssum[w] = sum; }
    }
    __syncthreads();

    if (t < 256)
        out[(size_t)row * 256 + t] = expf(v - smax[sg]) / ssum[sg];
}

// ---------------------------------------------------------------------------
// Launch
// ---------------------------------------------------------------------------
extern "C" void kernel_launch(void* const* d_in, const int* in_sizes, int n_in,
                              void* d_out, int out_size)
{
    const float* x   = (const float*)d_in[0];
    const float* W0  = (const float*)d_in[1];
    const float* b0  = (const float*)d_in[2];
    const float* g0  = (const float*)d_in[3];
    const float* be0 = (const float*)d_in[4];
    const float* rm0 = (const float*)d_in[5];
    const float* rv0 = (const float*)d_in[6];
    const float* W1  = (const float*)d_in[7];
    const float* b1  = (const float*)d_in[8];
    const float* g1  = (const float*)d_in[9];
    const float* be1 = (const float*)d_in[10];
    const float* rm1 = (const float*)d_in[11];
    const float* rv1 = (const float*)d_in[12];
    const float* W2  = (const float*)d_in[13];
    const float* b2  = (const float*)d_in[14];
    const float* g2  = (const float*)d_in[15];
    const float* be2 = (const float*)d_in[16];
    const float* rm2 = (const float*)d_in[17];
    const float* rv2 = (const float*)d_in[18];
    const float* W3  = (const float*)d_in[19];
    const float* b3  = (const float*)d_in[20];
    const int*   seg = (const int*)d_in[21];

    __half *act = nullptr, *wh = nullptr;
    float* logits = nullptr;
    cudaGetSymbolAddress((void**)&act, g_act);
    cudaGetSymbolAddress((void**)&wh, g_w);
    cudaGetSymbolAddress((void**)&logits, g_logits);

    cudaFuncSetAttribute(mma_gemm_bn, cudaFuncAttributeMaxDynamicSharedMemorySize, SMEM_MAIN);
    cudaFuncSetAttribute(mma_gemm_l3, cudaFuncAttributeMaxDynamicSharedMemorySize, SMEM_L3);

    // prologue: all conversions in one launch (1024 x-blocks + 2336 w-blocks)
    cvt_all<<<3360, 256>>>(x, W0, W1, W2, W3);

    dim3 blk(256);
    dim3 grid1024(1024 / TBN, B_ROWS / TBM);   // (8, 64)
    dim3 gridL3(256 / L3_TBN, B_ROWS / TBM);   // (4, 64)

    mma_gemm_bn<<<grid1024, blk, SMEM_MAIN>>>(act + 3072, wh + WOFF0,
                                              b0, g0, be0, rm0, rv0,
                                              act + 2048, 256);
    mma_gemm_bn<<<grid1024, blk, SMEM_MAIN>>>(act + 2048, wh + WOFF1,
                                              b1, g1, be1, rm1, rv1,
                                              act + 1024, 1280);
    mma_gemm_bn<<<grid1024, blk, SMEM_MAIN>>>(act + 1024, wh + WOFF2,
                                              b2, g2, be2, rm2, rv2,
                                              act, 2304);
    mma_gemm_l3<<<gridL3, blk, SMEM_L3>>>(act, wh + WOFF3, b3, logits, 3328);

    seg_softmax_kernel<<<B_ROWS, 320>>>(seg, (float*)d_out);
}